// round 13
// baseline (speedup 1.0000x reference)
#include <cuda_runtime.h>
#include <cstdint>

// Problem constants
#define BB    8
#define PNN   16384
#define NSS   256
#define KDIMC 512
#define HIDC  384
#define HALFC 192
#define CIN1  576            // HID + HALF
#define MROWS (BB*NSS)       // 2048
#define EPSC  1e-5f

// ---------------- scratch (device globals; no allocation allowed) ----------
__device__ float               g_L[6];                 // chol(G)
__device__ __align__(16) float g_gf[BB*HIDC];
__device__ int                 g_sel[BB*NSS];
__device__ __align__(16) float4 g_pts[BB*PNN];         // reordered u-coords
__device__ int                 g_oidx[BB*PNN];
__device__ __align__(16) float g_A0[HIDC];             // conv1 collapse coeffs
__device__ __align__(16) float g_A1[HIDC];
__device__ __align__(16) float g_A2[HIDC];
__device__ __align__(16) float g_A3[HIDC];
__device__ __align__(16) float g_gfc[BB*HIDC];
__device__ __align__(16) float g_h1[MROWS*HIDC];
__device__ __align__(16) float g_h2[MROWS*HIDC];
__device__ __align__(16) float g_psum[8*HIDC];
__device__ __align__(16) float g_psq[8*HIDC];
__device__ __align__(16) float g_sc2[HIDC];
__device__ __align__(16) float g_sh2[HIDC];

// ---------------- helpers ---------------------------------------------------
__device__ __forceinline__ unsigned fenc(float f){
    unsigned u = __float_as_uint(f);
    return u ^ (unsigned)(((int)u >> 31) | 0x80000000);
}
__device__ __forceinline__ float fdec(unsigned u){
    unsigned b = (u & 0x80000000u) ? (u ^ 0x80000000u) : ~u;
    return __uint_as_float(b);
}
__device__ __forceinline__ int morton3(int x, int y, int z){
    int m = 0;
#pragma unroll
    for (int i = 0; i < 3; i++)
        m |= ((x>>i&1)<<(3*i+2)) | ((y>>i&1)<<(3*i+1)) | ((z>>i&1)<<(3*i));
    return m;
}
__device__ __forceinline__ unsigned long long pk2(float lo, float hi){
    unsigned long long r;
    asm("mov.b64 %0, {%1, %2};" : "=l"(r) : "f"(lo), "f"(hi));
    return r;
}
__device__ __forceinline__ void upk2(unsigned long long v, float& lo, float& hi){
    asm("mov.b64 {%0, %1}, %2;" : "=f"(lo), "=f"(hi) : "l"(v));
}
__device__ __forceinline__ unsigned long long fma2(unsigned long long a,
                                                   unsigned long long b,
                                                   unsigned long long c){
    unsigned long long r;
    asm("fma.rn.f32x2 %0, %1, %2, %3;" : "=l"(r) : "l"(a), "l"(b), "l"(c));
    return r;
}
__device__ __forceinline__ unsigned long long add2(unsigned long long a,
                                                   unsigned long long b){
    unsigned long long r;
    asm("add.rn.f32x2 %0, %1, %2;" : "=l"(r) : "l"(a), "l"(b));
    return r;
}
__device__ __forceinline__ unsigned long long mul2(unsigned long long a,
                                                   unsigned long long b){
    unsigned long long r;
    asm("mul.rn.f32x2 %0, %1, %2;" : "=l"(r) : "l"(a), "l"(b));
    return r;
}

// ---------------- G = Wc @ Wc^T, then Cholesky ------------------------------
__global__ void k_gram(const float* __restrict__ Wc){
    __shared__ float sG[9];
    const int pa[6] = {0,0,0,1,1,2};
    const int pb[6] = {0,1,2,1,2,2};
    int w = threadIdx.x >> 5, lane = threadIdx.x & 31;
    if (w < 6){
        float s = 0.f;
        for (int k = lane; k < HALFC; k += 32)
            s = fmaf(Wc[pa[w]*HALFC + k], Wc[pb[w]*HALFC + k], s);
#pragma unroll
        for (int o = 16; o > 0; o >>= 1) s += __shfl_down_sync(0xffffffffu, s, o);
        if (lane == 0){ sG[pa[w]*3+pb[w]] = s; sG[pb[w]*3+pa[w]] = s; }
    }
    __syncthreads();
    if (threadIdx.x == 0){
        float G00=sG[0],G01=sG[1],G02=sG[2],G11=sG[4],G12=sG[5],G22=sG[8];
        float L00 = sqrtf(G00);
        float L10 = G01 / L00;
        float L20 = G02 / L00;
        float L11 = sqrtf(G11 - L10*L10);
        float L21 = (G12 - L10*L20) / L11;
        float L22 = sqrtf(G22 - L20*L20 - L21*L21);
        g_L[0]=L00; g_L[1]=L10; g_L[2]=L20; g_L[3]=L11; g_L[4]=L21; g_L[5]=L22;
    }
}

// ---------------- global_feat = pf @ W_feat + b_feat  (8 x 384) ------------
__global__ void k_gf(const float* __restrict__ pf, const float* __restrict__ Wf,
                     const float* __restrict__ bf){
    __shared__ float sp[KDIMC];
    int b = blockIdx.x, t = threadIdx.x;
    for (int k = t; k < KDIMC; k += blockDim.x) sp[k] = pf[b*KDIMC + k];
    __syncthreads();
    float acc = bf[t];
#pragma unroll 4
    for (int k = 0; k < KDIMC; k++)
        acc = fmaf(sp[k], Wf[k*HIDC + t], acc);
    g_gf[b*HIDC + t] = acc;
}

// ---------------- k_prep: u = L^T p, Morton counting sort ------------------
__global__ __launch_bounds__(1024) void k_prep(const float* __restrict__ P){
    __shared__ unsigned s_bb[6];
    __shared__ int s_hist[512];
    __shared__ int s_off[512];
    __shared__ int s_wsum[16];
    __shared__ float s_lo[3], s_iv[3];

    int b = blockIdx.x, t = threadIdx.x;
    int lane = t & 31;
    float L00=g_L[0],L10=g_L[1],L20=g_L[2],L11=g_L[3],L21=g_L[4],L22=g_L[5];
    const float* pb = P + (size_t)b*PNN*3;

    if (t < 3)            s_bb[t] = 0xFFFFFFFFu;
    else if (t < 6)       s_bb[t] = 0u;
    if (t < 512) s_hist[t] = 0;
    __syncthreads();

    float mn[3] = {1e30f,1e30f,1e30f}, mx[3] = {-1e30f,-1e30f,-1e30f};
#pragma unroll
    for (int k = 0; k < 16; k++){
        int idx = t + k*1024;
        float px=pb[idx*3+0], py=pb[idx*3+1], pz=pb[idx*3+2];
        float u0 = fmaf(L00,px, fmaf(L10,py, L20*pz));
        float u1 = fmaf(L11,py, L21*pz);
        float u2 = L22*pz;
        mn[0]=fminf(mn[0],u0); mx[0]=fmaxf(mx[0],u0);
        mn[1]=fminf(mn[1],u1); mx[1]=fmaxf(mx[1],u1);
        mn[2]=fminf(mn[2],u2); mx[2]=fmaxf(mx[2],u2);
    }
#pragma unroll
    for (int d = 0; d < 3; d++){
        unsigned emn = __reduce_min_sync(0xffffffffu, fenc(mn[d]));
        unsigned emx = __reduce_max_sync(0xffffffffu, fenc(mx[d]));
        if (lane == 0){ atomicMin(&s_bb[d], emn); atomicMax(&s_bb[3+d], emx); }
    }
    __syncthreads();
    if (t < 3){
        float lo = fdec(s_bb[t]), hi = fdec(s_bb[3+t]);
        s_lo[t] = lo;
        s_iv[t] = 8.0f / fmaxf(hi - lo, 1e-20f);
    }
    __syncthreads();

    float lo0=s_lo[0], lo1=s_lo[1], lo2=s_lo[2];
    float iv0=s_iv[0], iv1=s_iv[1], iv2=s_iv[2];
    int cell[16];
#pragma unroll
    for (int k = 0; k < 16; k++){
        int idx = t + k*1024;
        float px=pb[idx*3+0], py=pb[idx*3+1], pz=pb[idx*3+2];
        float u0 = fmaf(L00,px, fmaf(L10,py, L20*pz));
        float u1 = fmaf(L11,py, L21*pz);
        float u2 = L22*pz;
        int c0 = min(7, max(0, (int)((u0-lo0)*iv0)));
        int c1 = min(7, max(0, (int)((u1-lo1)*iv1)));
        int c2 = min(7, max(0, (int)((u2-lo2)*iv2)));
        cell[k] = morton3(c0, c1, c2);
        atomicAdd(&s_hist[cell[k]], 1);
    }
    __syncthreads();

    if (t < 512){
        int v = s_hist[t], inc = v;
#pragma unroll
        for (int o = 1; o < 32; o <<= 1){
            int n = __shfl_up_sync(0xffffffffu, inc, o);
            if (lane >= o) inc += n;
        }
        if (lane == 31) s_wsum[t >> 5] = inc;
        s_off[t] = inc - v;
    }
    __syncthreads();
    if (t < 16){
        int v = s_wsum[t], inc = v;
#pragma unroll
        for (int o = 1; o < 16; o <<= 1){
            int n = __shfl_up_sync(0xffffu, inc, o);
            if (t >= o) inc += n;
        }
        s_wsum[t] = inc - v;
    }
    __syncthreads();
    if (t < 512) s_off[t] += s_wsum[t >> 5];
    __syncthreads();

#pragma unroll
    for (int k = 0; k < 16; k++){
        int idx = t + k*1024;
        float px=pb[idx*3+0], py=pb[idx*3+1], pz=pb[idx*3+2];
        float u0 = fmaf(L00,px, fmaf(L10,py, L20*pz));
        float u1 = fmaf(L11,py, L21*pz);
        float u2 = L22*pz;
        int pos = atomicAdd(&s_off[cell[k]], 1);
        g_pts[b*PNN + pos]  = make_float4(u0, u1, u2, 0.f);
        g_oidx[b*PNN + pos] = idx;
    }
}

// ---------------- FPS v5 (round-11 passing form, 242us) --------------------
// Packed fma2/add2/mul2 distance; scalar fminf/fmaxf min-update + max tree
// (min/max.f32x2 DO NOT exist on sm_103a — ptxas rejects them).
#define FPS_T 1024
#define FPS_K 16
#define SM_DIST 0
#define SM_Z    16384
#define SM_O    32768
#define SM_SLOT 49152            // u64[2][32] -> 128 floats
#define FPS_SMEM_FLOATS (49152 + 128)

__global__ __launch_bounds__(FPS_T, 1) void k_fps5(const float* __restrict__ P){
    extern __shared__ float sm[];
    float* smd = sm + SM_DIST;
    float* smz = sm + SM_Z;
    int*   smo = (int*)(sm + SM_O);
    unsigned long long* slot = (unsigned long long*)(sm + SM_SLOT); // [2][32]

    const int t = threadIdx.x, lane = t & 31, wid = t >> 5;
    const int b = blockIdx.x;
    const float4* gp = g_pts + (size_t)b*PNN;

    float uxs[FPS_K], uys[FPS_K];
    float bl0=1e30f, bl1=1e30f, bl2=1e30f, bh0=-1e30f, bh1=-1e30f, bh2=-1e30f;
#pragma unroll
    for (int k = 0; k < FPS_K; k++){
        float4 v = gp[t*FPS_K + k];
        uxs[k] = v.x; uys[k] = v.y;
        int swo = (wid<<9) + ((k>>2)<<7) + (lane<<2) + (k&3);
        smz[swo] = v.z;
        smd[swo] = 1e10f;
        smo[swo] = g_oidx[b*PNN + t*FPS_K + k];
        bl0=fminf(bl0,v.x); bh0=fmaxf(bh0,v.x);
        bl1=fminf(bl1,v.y); bh1=fmaxf(bh1,v.y);
        bl2=fminf(bl2,v.z); bh2=fmaxf(bh2,v.z);
    }
    unsigned long long X2[8], Y2[8];
#pragma unroll
    for (int p = 0; p < 8; p++){
        X2[p] = pk2(uxs[2*p], uxs[2*p+1]);
        Y2[p] = pk2(uys[2*p], uys[2*p+1]);
    }
    bl0 = fdec(__reduce_min_sync(0xffffffffu, fenc(bl0)));
    bl1 = fdec(__reduce_min_sync(0xffffffffu, fenc(bl1)));
    bl2 = fdec(__reduce_min_sync(0xffffffffu, fenc(bl2)));
    bh0 = fdec(__reduce_max_sync(0xffffffffu, fenc(bh0)));
    bh1 = fdec(__reduce_max_sync(0xffffffffu, fenc(bh1)));
    bh2 = fdec(__reduce_max_sync(0xffffffffu, fenc(bh2)));

    const float* p0 = P + (size_t)b*PNN*3;
    float px0=p0[0], py0=p0[1], pz0=p0[2];
    float cx = fmaf(g_L[0],px0, fmaf(g_L[1],py0, g_L[2]*pz0));
    float cy = fmaf(g_L[3],py0, g_L[4]*pz0);
    float cz = g_L[5]*pz0;
    if (t == 0) g_sel[b*NSS] = 0;
    __syncthreads();

    unsigned            wub  = 0xFFFFFFFFu;
    unsigned long long  wkey = 0ull;

    for (int j = 0; j < NSS-1; j++){
        float e0 = fmaxf(fmaxf(bl0-cx, cx-bh0), 0.f);
        float e1 = fmaxf(fmaxf(bl1-cy, cy-bh1), 0.f);
        float e2 = fmaxf(fmaxf(bl2-cz, cz-bh2), 0.f);
        float lb = fmaf(e0,e0, fmaf(e1,e1, e2*e2));

        if (__float_as_uint(lb) < wub){
            unsigned long long mcx2 = pk2(-cx,-cx);
            unsigned long long mcy2 = pk2(-cy,-cy);
            unsigned long long mcz2 = pk2(-cz,-cz);
            float gm[4]; float ub;
#pragma unroll
            for (int g = 0; g < 4; g++){
                int swo = (wid<<9) + (g<<7) + (lane<<2);
                ulonglong2 z2 = *(ulonglong2*)(smz + swo);
                float4 dd = *(float4*)(smd + swo);
                unsigned long long ax = add2(X2[2*g],   mcx2);
                unsigned long long ay = add2(Y2[2*g],   mcy2);
                unsigned long long az = add2(z2.x,      mcz2);
                unsigned long long d2 = fma2(ax,ax, fma2(ay,ay, mul2(az,az)));
                float d0, d1; upk2(d2, d0, d1);
                dd.x = fminf(dd.x, d0); dd.y = fminf(dd.y, d1);
                ax = add2(X2[2*g+1], mcx2);
                ay = add2(Y2[2*g+1], mcy2);
                az = add2(z2.y,      mcz2);
                d2 = fma2(ax,ax, fma2(ay,ay, mul2(az,az)));
                upk2(d2, d0, d1);
                dd.z = fminf(dd.z, d0); dd.w = fminf(dd.w, d1);
                *(float4*)(smd + swo) = dd;
                gm[g] = fmaxf(fmaxf(dd.x,dd.y), fmaxf(dd.z,dd.w));
            }
            ub = fmaxf(fmaxf(gm[0],gm[1]), fmaxf(gm[2],gm[3]));
            wub = __reduce_max_sync(0xffffffffu, __float_as_uint(ub));

            unsigned cand = 0u;
            if (__float_as_uint(ub) == wub){
#pragma unroll
                for (int g = 0; g < 4; g++){
                    if (__float_as_uint(gm[g]) == wub){
                        int swo = (wid<<9) + (g<<7) + (lane<<2);
                        float4 dd = *(float4*)(smd + swo);
                        int4   oo = *(int4*)  (smo + swo);
                        unsigned rb = (unsigned)(t*FPS_K + g*4);
                        if (__float_as_uint(dd.x)==wub)
                            cand = max(cand, ((0x3FFFu-(unsigned)oo.x)<<14)|(rb+0));
                        if (__float_as_uint(dd.y)==wub)
                            cand = max(cand, ((0x3FFFu-(unsigned)oo.y)<<14)|(rb+1));
                        if (__float_as_uint(dd.z)==wub)
                            cand = max(cand, ((0x3FFFu-(unsigned)oo.z)<<14)|(rb+2));
                        if (__float_as_uint(dd.w)==wub)
                            cand = max(cand, ((0x3FFFu-(unsigned)oo.w)<<14)|(rb+3));
                    }
                }
            }
            unsigned wlo = __reduce_max_sync(0xffffffffu, cand);
            wkey = ((unsigned long long)wub << 32) | wlo;
        }
        if (lane == 0) slot[((j&1)<<5) + wid] = wkey;
        __syncthreads();

        unsigned long long kk = slot[((j&1)<<5) + lane];
        unsigned hi = (unsigned)(kk >> 32), lo = (unsigned)kk;
        unsigned gh = __reduce_max_sync(0xffffffffu, hi);
        unsigned gl = __reduce_max_sync(0xffffffffu, (hi==gh) ? lo : 0u);

        int r = (int)(gl & 0x3FFFu);
        float4 cp = gp[r];
        cx = cp.x; cy = cp.y; cz = cp.z;
        if (t == 0) g_sel[b*NSS + j + 1] = (int)(0x3FFFu - (gl >> 14));
    }
}

// ---------------- conv1 collapse precompute --------------------------------
__global__ __launch_bounds__(192) void k_pre1(const float* __restrict__ Wc,
                                              const float* __restrict__ bc,
                                              const float* __restrict__ W1,
                                              const float* __restrict__ b1){
    __shared__ float sred[6][4];
    int o = blockIdx.x, c = threadIdx.x;
    int lane = c & 31, w = c >> 5;
    float w1v = W1[(size_t)o*CIN1 + HIDC + c];
    float s0 = Wc[c]           * w1v;
    float s1 = Wc[HALFC + c]   * w1v;
    float s2 = Wc[2*HALFC + c] * w1v;
    float s3 = bc[c]           * w1v;
#pragma unroll
    for (int off = 16; off > 0; off >>= 1){
        s0 += __shfl_down_sync(0xffffffffu, s0, off);
        s1 += __shfl_down_sync(0xffffffffu, s1, off);
        s2 += __shfl_down_sync(0xffffffffu, s2, off);
        s3 += __shfl_down_sync(0xffffffffu, s3, off);
    }
    if (lane == 0){ sred[w][0]=s0; sred[w][1]=s1; sred[w][2]=s2; sred[w][3]=s3; }
    __syncthreads();
    if (c == 0){
        float a0=0,a1=0,a2=0,a3=0;
#pragma unroll
        for (int i = 0; i < 6; i++){ a0+=sred[i][0]; a1+=sred[i][1]; a2+=sred[i][2]; a3+=sred[i][3]; }
        g_A0[o]=a0; g_A1[o]=a1; g_A2[o]=a2; g_A3[o]=a3+b1[o];
    }
}

// gfc[b][o] = gf[b] . W1[o][:384]  (warp-per-row, coalesced)
__global__ __launch_bounds__(256) void k_pre2(const float* __restrict__ W1){
    int b = blockIdx.y;
    int w = threadIdx.x >> 5, lane = threadIdx.x & 31;
    int o = blockIdx.x * 8 + w;
    const float* row = W1 + (size_t)o*CIN1;
    const float* gfb = g_gf + b*HIDC;
    float acc = 0.f;
#pragma unroll
    for (int it = 0; it < 12; it++){
        int c = it*32 + lane;
        acc = fmaf(gfb[c], row[c], acc);
    }
#pragma unroll
    for (int off = 16; off > 0; off >>= 1)
        acc += __shfl_down_sync(0xffffffffu, acc, off);
    if (lane == 0) g_gfc[b*HIDC + o] = acc;
}

// ---------------- h1 build: rank-4 update per selected point ---------------
__global__ __launch_bounds__(256) void k_h1(const float* __restrict__ P){
    int f = blockIdx.x * 256 + threadIdx.x;       // float4 idx, 2048*96 total
    int n = f / 96, c4 = (f % 96) * 4;
    int b = n >> 8;
    int sidx = g_sel[n];
    const float* pp = P + ((size_t)b*PNN + sidx)*3;
    float x = pp[0], y = pp[1], z = pp[2];
    float4 a0 = *(const float4*)&g_A0[c4];
    float4 a1 = *(const float4*)&g_A1[c4];
    float4 a2 = *(const float4*)&g_A2[c4];
    float4 a3 = *(const float4*)&g_A3[c4];
    float4 gc = *(const float4*)&g_gfc[b*HIDC + c4];
    float4 v;
    v.x = gc.x + fmaf(x,a0.x, fmaf(y,a1.x, fmaf(z,a2.x, a3.x)));
    v.y = gc.y + fmaf(x,a0.y, fmaf(y,a1.y, fmaf(z,a2.y, a3.y)));
    v.z = gc.z + fmaf(x,a0.z, fmaf(y,a1.z, fmaf(z,a2.z, a3.z)));
    v.w = gc.w + fmaf(x,a0.w, fmaf(y,a1.w, fmaf(z,a2.w, a3.w)));
    *(float4*)&g_h1[(size_t)n*HIDC + c4] = v;
}

// ---------------- BN stats partial pass ------------------------------------
__global__ __launch_bounds__(256) void k_statsp(int mode){
    const float* X = (mode == 0) ? g_h1 : g_h2;
    __shared__ float ssum[256], ssq[256];
    int cl = threadIdx.x & 31;
    int rg = threadIdx.x >> 5;
    int c  = blockIdx.x * 32 + cl;
    int r0 = blockIdx.y * 256;
    float s = 0.f, q = 0.f;
    for (int r = r0 + rg; r < r0 + 256; r += 8){
        float v = X[(size_t)r*HIDC + c];
        s += v; q = fmaf(v, v, q);
    }
    ssum[threadIdx.x] = s; ssq[threadIdx.x] = q;
    __syncthreads();
    if (rg == 0){
#pragma unroll
        for (int i = 1; i < 8; i++){ s += ssum[i*32 + cl]; q += ssq[i*32 + cl]; }
        g_psum[blockIdx.y*HIDC + c] = s;
        g_psq [blockIdx.y*HIDC + c] = q;
    }
}
__global__ __launch_bounds__(HIDC) void k_statsr(const float* __restrict__ g,
                                                 const float* __restrict__ be){
    int c = threadIdx.x;
    float s = 0.f, q = 0.f;
#pragma unroll
    for (int i = 0; i < 8; i++){
        s += g_psum[i*HIDC + c];
        q += g_psq [i*HIDC + c];
    }
    float mean = s * (1.f/MROWS);
    float var  = q * (1.f/MROWS) - mean*mean;
    float sv   = g[c] * rsqrtf(var + EPSC);
    g_sc2[c] = sv;
    g_sh2[c] = fmaf(-mean, sv, be[c]);
}

// ---------------- GEMM2 (BN1 stats fused in prologue) ----------------------
__global__ __launch_bounds__(256) void k_gemm(const float* __restrict__ Wt,
                                              const float* __restrict__ bias,
                                              const float* __restrict__ g1,
                                              const float* __restrict__ be1)
{
    const int BM=64, BN=64, BK=16, K=HIDC;
    __shared__ float As[BK][BM];
    __shared__ float Bs[BK][BN];
    __shared__ float ssc[HIDC], ssh[HIDC];

    for (int c = threadIdx.x; c < HIDC; c += 256){
        float s = 0.f, q = 0.f;
#pragma unroll
        for (int i = 0; i < 8; i++){
            s += g_psum[i*HIDC + c];
            q += g_psq [i*HIDC + c];
        }
        float mean = s * (1.f/MROWS);
        float var  = q * (1.f/MROWS) - mean*mean;
        float sv   = g1[c] * rsqrtf(var + EPSC);
        ssc[c] = sv;
        ssh[c] = fmaf(-mean, sv, be1[c]);
    }
    __syncthreads();

    int tx = threadIdx.x & 15;
    int ty = threadIdx.x >> 4;
    int m0 = blockIdx.y * BM;
    int n0 = blockIdx.x * BN;
    int lr = threadIdx.x >> 2;
    int lk = (threadIdx.x & 3) * 4;

    float acc[4][4];
#pragma unroll
    for (int i=0;i<4;i++)
#pragma unroll
        for (int j=0;j<4;j++) acc[i][j]=0.f;

    for (int k0 = 0; k0 < K; k0 += BK){
        float4 av = *(const float4*)&g_h1[(size_t)(m0+lr)*K + k0 + lk];
        float4 sv = *(const float4*)&ssc[k0+lk];
        float4 hv = *(const float4*)&ssh[k0+lk];
        av.x = fmaxf(fmaf(av.x, sv.x, hv.x), 0.f);
        av.y = fmaxf(fmaf(av.y, sv.y, hv.y), 0.f);
        av.z = fmaxf(fmaf(av.z, sv.z, hv.z), 0.f);
        av.w = fmaxf(fmaf(av.w, sv.w, hv.w), 0.f);
        float4 bv = *(const float4*)&Wt[(size_t)(n0+lr)*K + k0 + lk];
        As[lk+0][lr]=av.x; As[lk+1][lr]=av.y; As[lk+2][lr]=av.z; As[lk+3][lr]=av.w;
        Bs[lk+0][lr]=bv.x; Bs[lk+1][lr]=bv.y; Bs[lk+2][lr]=bv.z; Bs[lk+3][lr]=bv.w;
        __syncthreads();
#pragma unroll
        for (int kk = 0; kk < BK; kk++){
            float4 a = *(const float4*)&As[kk][ty*4];
            float4 b = *(const float4*)&Bs[kk][tx*4];
            acc[0][0]=fmaf(a.x,b.x,acc[0][0]); acc[0][1]=fmaf(a.x,b.y,acc[0][1]);
            acc[0][2]=fmaf(a.x,b.z,acc[0][2]); acc[0][3]=fmaf(a.x,b.w,acc[0][3]);
            acc[1][0]=fmaf(a.y,b.x,acc[1][0]); acc[1][1]=fmaf(a.y,b.y,acc[1][1]);
            acc[1][2]=fmaf(a.y,b.z,acc[1][2]); acc[1][3]=fmaf(a.y,b.w,acc[1][3]);
            acc[2][0]=fmaf(a.z,b.x,acc[2][0]); acc[2][1]=fmaf(a.z,b.y,acc[2][1]);
            acc[2][2]=fmaf(a.z,b.z,acc[2][2]); acc[2][3]=fmaf(a.z,b.w,acc[2][3]);
            acc[3][0]=fmaf(a.w,b.x,acc[3][0]); acc[3][1]=fmaf(a.w,b.y,acc[3][1]);
            acc[3][2]=fmaf(a.w,b.z,acc[3][2]); acc[3][3]=fmaf(a.w,b.w,acc[3][3]);
        }
        __syncthreads();
    }
    float4 bb = *(const float4*)&bias[n0 + tx*4];
#pragma unroll
    for (int i = 0; i < 4; i++){
        float4 o;
        o.x = acc[i][0] + bb.x; o.y = acc[i][1] + bb.y;
        o.z = acc[i][2] + bb.z; o.w = acc[i][3] + bb.w;
        *(float4*)&g_h2[(size_t)(m0 + ty*4 + i)*HIDC + n0 + tx*4] = o;
    }
}

// ---------------- final: out = relu(bn2(h2)) -------------------------------
__global__ void k_final(float* __restrict__ out){
    int i = blockIdx.x * 256 + threadIdx.x;
    float4 v = ((const float4*)g_h2)[i];
    int c = (i*4) % HIDC;
    v.x = fmaxf(fmaf(v.x, g_sc2[c+0], g_sh2[c+0]), 0.f);
    v.y = fmaxf(fmaf(v.y, g_sc2[c+1], g_sh2[c+1]), 0.f);
    v.z = fmaxf(fmaf(v.z, g_sc2[c+2], g_sh2[c+2]), 0.f);
    v.w = fmaxf(fmaf(v.w, g_sc2[c+3], g_sh2[c+3]), 0.f);
    ((float4*)out)[i] = v;
}

// ---------------- launch ---------------------------------------------------
extern "C" void kernel_launch(void* const* d_in, const int* in_sizes, int n_in,
                              void* d_out, int out_size){
    (void)in_sizes; (void)n_in; (void)out_size;
    const float* p   = (const float*)d_in[0];
    const float* pf  = (const float*)d_in[2];
    const float* Wf  = (const float*)d_in[3];
    const float* bf  = (const float*)d_in[4];
    const float* Wc  = (const float*)d_in[5];
    const float* bc  = (const float*)d_in[6];
    const float* W1  = (const float*)d_in[7];
    const float* b1  = (const float*)d_in[8];
    const float* g1  = (const float*)d_in[9];
    const float* be1 = (const float*)d_in[10];
    const float* W2  = (const float*)d_in[11];
    const float* b2  = (const float*)d_in[12];
    const float* g2  = (const float*)d_in[13];
    const float* be2 = (const float*)d_in[14];
    float* out = (float*)d_out;

    cudaFuncSetAttribute(k_fps5, cudaFuncAttributeMaxDynamicSharedMemorySize,
                         FPS_SMEM_FLOATS * (int)sizeof(float));

    k_gram<<<1, 192>>>(Wc);
    k_gf<<<BB, HIDC>>>(pf, Wf, bf);
    k_pre1<<<HIDC, 192>>>(Wc, bc, W1, b1);
    k_pre2<<<dim3(HIDC/8, BB), 256>>>(W1);
    k_prep<<<BB, 1024>>>(p);
    k_fps5<<<BB, FPS_T, FPS_SMEM_FLOATS * sizeof(float)>>>(p);
    k_h1<<<(MROWS*96)/256, 256>>>(p);
    k_statsp<<<dim3(HIDC/32, 8), 256>>>(0);
    k_gemm<<<dim3(HIDC/64, MROWS/64), 256>>>(W2, b2, g1, be1);   // BN1 fused
    k_statsp<<<dim3(HIDC/32, 8), 256>>>(1);
    k_statsr<<<1, HIDC>>>(g2, be2);
    k_final<<<(MROWS*HIDC/4)/256, 256>>>(out);
}

// round 15
// speedup vs baseline: 1.0156x; 1.0156x over previous
#include <cuda_runtime.h>
#include <cstdint>

// Problem constants
#define BB    8
#define PNN   16384
#define NSS   256
#define KDIMC 512
#define HIDC  384
#define HALFC 192
#define CIN1  576            // HID + HALF
#define MROWS (BB*NSS)       // 2048
#define EPSC  1e-5f

// ---------------- scratch (device globals; no allocation allowed) ----------
__device__ float               g_L[6];                 // chol(G)
__device__ __align__(16) float g_gf[BB*HIDC];
__device__ int                 g_sel[BB*NSS];
__device__ __align__(16) float4 g_pts[BB*PNN];         // reordered u-coords
__device__ int                 g_oidx[BB*PNN];
__device__ __align__(16) float g_A0[HIDC];             // conv1 collapse coeffs
__device__ __align__(16) float g_A1[HIDC];
__device__ __align__(16) float g_A2[HIDC];
__device__ __align__(16) float g_A3[HIDC];
__device__ __align__(16) float g_gfc[BB*HIDC];
__device__ __align__(16) float g_h1[MROWS*HIDC];
__device__ __align__(16) float g_h2[MROWS*HIDC];
__device__ __align__(16) float g_psum[8*HIDC];
__device__ __align__(16) float g_psq[8*HIDC];

// ---------------- helpers ---------------------------------------------------
__device__ __forceinline__ unsigned fenc(float f){
    unsigned u = __float_as_uint(f);
    return u ^ (unsigned)(((int)u >> 31) | 0x80000000);
}
__device__ __forceinline__ float fdec(unsigned u){
    unsigned b = (u & 0x80000000u) ? (u ^ 0x80000000u) : ~u;
    return __uint_as_float(b);
}
__device__ __forceinline__ int morton3(int x, int y, int z){
    int m = 0;
#pragma unroll
    for (int i = 0; i < 3; i++)
        m |= ((x>>i&1)<<(3*i+2)) | ((y>>i&1)<<(3*i+1)) | ((z>>i&1)<<(3*i));
    return m;
}
__device__ __forceinline__ unsigned long long pk2(float lo, float hi){
    unsigned long long r;
    asm("mov.b64 %0, {%1, %2};" : "=l"(r) : "f"(lo), "f"(hi));
    return r;
}
__device__ __forceinline__ void upk2(unsigned long long v, float& lo, float& hi){
    asm("mov.b64 {%0, %1}, %2;" : "=f"(lo), "=f"(hi) : "l"(v));
}
__device__ __forceinline__ unsigned long long fma2(unsigned long long a,
                                                   unsigned long long b,
                                                   unsigned long long c){
    unsigned long long r;
    asm("fma.rn.f32x2 %0, %1, %2, %3;" : "=l"(r) : "l"(a), "l"(b), "l"(c));
    return r;
}
__device__ __forceinline__ unsigned long long add2(unsigned long long a,
                                                   unsigned long long b){
    unsigned long long r;
    asm("add.rn.f32x2 %0, %1, %2;" : "=l"(r) : "l"(a), "l"(b));
    return r;
}
__device__ __forceinline__ unsigned long long mul2(unsigned long long a,
                                                   unsigned long long b){
    unsigned long long r;
    asm("mul.rn.f32x2 %0, %1, %2;" : "=l"(r) : "l"(a), "l"(b));
    return r;
}

// ---------------- setup1: gram+chol (block 0) | global_feat (blocks 1..8) --
__global__ __launch_bounds__(384) void k_setup1(const float* __restrict__ Wc,
                                                const float* __restrict__ pf,
                                                const float* __restrict__ Wf,
                                                const float* __restrict__ bf){
    if (blockIdx.x == 0){
        __shared__ float sG[9];
        const int pa[6] = {0,0,0,1,1,2};
        const int pb[6] = {0,1,2,1,2,2};
        int w = threadIdx.x >> 5, lane = threadIdx.x & 31;
        if (w < 6){
            float s = 0.f;
            for (int k = lane; k < HALFC; k += 32)
                s = fmaf(Wc[pa[w]*HALFC + k], Wc[pb[w]*HALFC + k], s);
#pragma unroll
            for (int o = 16; o > 0; o >>= 1) s += __shfl_down_sync(0xffffffffu, s, o);
            if (lane == 0){ sG[pa[w]*3+pb[w]] = s; sG[pb[w]*3+pa[w]] = s; }
        }
        __syncthreads();
        if (threadIdx.x == 0){
            float G00=sG[0],G01=sG[1],G02=sG[2],G11=sG[4],G12=sG[5],G22=sG[8];
            float L00 = sqrtf(G00);
            float L10 = G01 / L00;
            float L20 = G02 / L00;
            float L11 = sqrtf(G11 - L10*L10);
            float L21 = (G12 - L10*L20) / L11;
            float L22 = sqrtf(G22 - L20*L20 - L21*L21);
            g_L[0]=L00; g_L[1]=L10; g_L[2]=L20; g_L[3]=L11; g_L[4]=L21; g_L[5]=L22;
        }
    } else {
        __shared__ float sp[KDIMC];
        int b = blockIdx.x - 1, t = threadIdx.x;
        for (int k = t; k < KDIMC; k += 384) sp[k] = pf[b*KDIMC + k];
        __syncthreads();
        float acc = bf[t];
#pragma unroll 4
        for (int k = 0; k < KDIMC; k++)
            acc = fmaf(sp[k], Wf[k*HIDC + t], acc);
        g_gf[b*HIDC + t] = acc;
    }
}

// ---------------- setup2: pre1 (y=0) | pre2 (y=1) --------------------------
// pre1: A_i[o] = Wc[i].W1[o][384:], A3[o] = bc.W1[o][384:] + b1[o]
// pre2: gfc[b][o] = gf[b].W1[o][:384]  (warp-per-row, coalesced)
__global__ __launch_bounds__(256) void k_setup2(const float* __restrict__ Wc,
                                                const float* __restrict__ bc,
                                                const float* __restrict__ W1,
                                                const float* __restrict__ b1){
    if (blockIdx.y == 0){
        __shared__ float sred[6][4];
        int o = blockIdx.x, c = threadIdx.x;
        if (c < 192){
            int lane = c & 31, w = c >> 5;
            float w1v = W1[(size_t)o*CIN1 + HIDC + c];
            float s0 = Wc[c]           * w1v;
            float s1 = Wc[HALFC + c]   * w1v;
            float s2 = Wc[2*HALFC + c] * w1v;
            float s3 = bc[c]           * w1v;
#pragma unroll
            for (int off = 16; off > 0; off >>= 1){
                s0 += __shfl_down_sync(0xffffffffu, s0, off);
                s1 += __shfl_down_sync(0xffffffffu, s1, off);
                s2 += __shfl_down_sync(0xffffffffu, s2, off);
                s3 += __shfl_down_sync(0xffffffffu, s3, off);
            }
            if (lane == 0){ sred[w][0]=s0; sred[w][1]=s1; sred[w][2]=s2; sred[w][3]=s3; }
        }
        __syncthreads();
        if (threadIdx.x == 0){
            float a0=0,a1=0,a2=0,a3=0;
#pragma unroll
            for (int i = 0; i < 6; i++){ a0+=sred[i][0]; a1+=sred[i][1]; a2+=sred[i][2]; a3+=sred[i][3]; }
            g_A0[o]=a0; g_A1[o]=a1; g_A2[o]=a2; g_A3[o]=a3+b1[o];
        }
    } else {
        // blockIdx.x in [0,384): 8 warps -> 8 output rows; b = x % 8 pattern:
        // use x = ob*8 + b mapping: ob = x >> 3, b = x & 7
        int b  = blockIdx.x & 7;
        int ob = blockIdx.x >> 3;                   // 0..47
        int w = threadIdx.x >> 5, lane = threadIdx.x & 31;
        int o = ob * 8 + w;
        const float* row = W1 + (size_t)o*CIN1;
        const float* gfb = g_gf + b*HIDC;
        float acc = 0.f;
#pragma unroll
        for (int it = 0; it < 12; it++){
            int c = it*32 + lane;
            acc = fmaf(gfb[c], row[c], acc);
        }
#pragma unroll
        for (int off = 16; off > 0; off >>= 1)
            acc += __shfl_down_sync(0xffffffffu, acc, off);
        if (lane == 0) g_gfc[b*HIDC + o] = acc;
    }
}

// ---------------- k_prep: u = L^T p, Morton counting sort ------------------
__global__ __launch_bounds__(1024) void k_prep(const float* __restrict__ P){
    __shared__ unsigned s_bb[6];
    __shared__ int s_hist[512];
    __shared__ int s_off[512];
    __shared__ int s_wsum[16];
    __shared__ float s_lo[3], s_iv[3];

    int b = blockIdx.x, t = threadIdx.x;
    int lane = t & 31;
    float L00=g_L[0],L10=g_L[1],L20=g_L[2],L11=g_L[3],L21=g_L[4],L22=g_L[5];
    const float* pb = P + (size_t)b*PNN*3;

    if (t < 3)            s_bb[t] = 0xFFFFFFFFu;
    else if (t < 6)       s_bb[t] = 0u;
    if (t < 512) s_hist[t] = 0;
    __syncthreads();

    float mn[3] = {1e30f,1e30f,1e30f}, mx[3] = {-1e30f,-1e30f,-1e30f};
#pragma unroll
    for (int k = 0; k < 16; k++){
        int idx = t + k*1024;
        float px=pb[idx*3+0], py=pb[idx*3+1], pz=pb[idx*3+2];
        float u0 = fmaf(L00,px, fmaf(L10,py, L20*pz));
        float u1 = fmaf(L11,py, L21*pz);
        float u2 = L22*pz;
        mn[0]=fminf(mn[0],u0); mx[0]=fmaxf(mx[0],u0);
        mn[1]=fminf(mn[1],u1); mx[1]=fmaxf(mx[1],u1);
        mn[2]=fminf(mn[2],u2); mx[2]=fmaxf(mx[2],u2);
    }
#pragma unroll
    for (int d = 0; d < 3; d++){
        unsigned emn = __reduce_min_sync(0xffffffffu, fenc(mn[d]));
        unsigned emx = __reduce_max_sync(0xffffffffu, fenc(mx[d]));
        if (lane == 0){ atomicMin(&s_bb[d], emn); atomicMax(&s_bb[3+d], emx); }
    }
    __syncthreads();
    if (t < 3){
        float lo = fdec(s_bb[t]), hi = fdec(s_bb[3+t]);
        s_lo[t] = lo;
        s_iv[t] = 8.0f / fmaxf(hi - lo, 1e-20f);
    }
    __syncthreads();

    float lo0=s_lo[0], lo1=s_lo[1], lo2=s_lo[2];
    float iv0=s_iv[0], iv1=s_iv[1], iv2=s_iv[2];
    int cell[16];
#pragma unroll
    for (int k = 0; k < 16; k++){
        int idx = t + k*1024;
        float px=pb[idx*3+0], py=pb[idx*3+1], pz=pb[idx*3+2];
        float u0 = fmaf(L00,px, fmaf(L10,py, L20*pz));
        float u1 = fmaf(L11,py, L21*pz);
        float u2 = L22*pz;
        int c0 = min(7, max(0, (int)((u0-lo0)*iv0)));
        int c1 = min(7, max(0, (int)((u1-lo1)*iv1)));
        int c2 = min(7, max(0, (int)((u2-lo2)*iv2)));
        cell[k] = morton3(c0, c1, c2);
        atomicAdd(&s_hist[cell[k]], 1);
    }
    __syncthreads();

    if (t < 512){
        int v = s_hist[t], inc = v;
#pragma unroll
        for (int o = 1; o < 32; o <<= 1){
            int n = __shfl_up_sync(0xffffffffu, inc, o);
            if (lane >= o) inc += n;
        }
        if (lane == 31) s_wsum[t >> 5] = inc;
        s_off[t] = inc - v;
    }
    __syncthreads();
    if (t < 16){
        int v = s_wsum[t], inc = v;
#pragma unroll
        for (int o = 1; o < 16; o <<= 1){
            int n = __shfl_up_sync(0xffffu, inc, o);
            if (t >= o) inc += n;
        }
        s_wsum[t] = inc - v;
    }
    __syncthreads();
    if (t < 512) s_off[t] += s_wsum[t >> 5];
    __syncthreads();

#pragma unroll
    for (int k = 0; k < 16; k++){
        int idx = t + k*1024;
        float px=pb[idx*3+0], py=pb[idx*3+1], pz=pb[idx*3+2];
        float u0 = fmaf(L00,px, fmaf(L10,py, L20*pz));
        float u1 = fmaf(L11,py, L21*pz);
        float u2 = L22*pz;
        int pos = atomicAdd(&s_off[cell[k]], 1);
        g_pts[b*PNN + pos]  = make_float4(u0, u1, u2, 0.f);
        g_oidx[b*PNN + pos] = idx;
    }
}

// ---------------- FPS v5 (frozen: proven 242us) ----------------------------
#define FPS_T 1024
#define FPS_K 16
#define SM_DIST 0
#define SM_Z    16384
#define SM_O    32768
#define SM_SLOT 49152            // u64[2][32] -> 128 floats
#define FPS_SMEM_FLOATS (49152 + 128)

__global__ __launch_bounds__(FPS_T, 1) void k_fps5(const float* __restrict__ P){
    extern __shared__ float sm[];
    float* smd = sm + SM_DIST;
    float* smz = sm + SM_Z;
    int*   smo = (int*)(sm + SM_O);
    unsigned long long* slot = (unsigned long long*)(sm + SM_SLOT); // [2][32]

    const int t = threadIdx.x, lane = t & 31, wid = t >> 5;
    const int b = blockIdx.x;
    const float4* gp = g_pts + (size_t)b*PNN;

    float uxs[FPS_K], uys[FPS_K];
    float bl0=1e30f, bl1=1e30f, bl2=1e30f, bh0=-1e30f, bh1=-1e30f, bh2=-1e30f;
#pragma unroll
    for (int k = 0; k < FPS_K; k++){
        float4 v = gp[t*FPS_K + k];
        uxs[k] = v.x; uys[k] = v.y;
        int swo = (wid<<9) + ((k>>2)<<7) + (lane<<2) + (k&3);
        smz[swo] = v.z;
        smd[swo] = 1e10f;
        smo[swo] = g_oidx[b*PNN + t*FPS_K + k];
        bl0=fminf(bl0,v.x); bh0=fmaxf(bh0,v.x);
        bl1=fminf(bl1,v.y); bh1=fmaxf(bh1,v.y);
        bl2=fminf(bl2,v.z); bh2=fmaxf(bh2,v.z);
    }
    unsigned long long X2[8], Y2[8];
#pragma unroll
    for (int p = 0; p < 8; p++){
        X2[p] = pk2(uxs[2*p], uxs[2*p+1]);
        Y2[p] = pk2(uys[2*p], uys[2*p+1]);
    }
    bl0 = fdec(__reduce_min_sync(0xffffffffu, fenc(bl0)));
    bl1 = fdec(__reduce_min_sync(0xffffffffu, fenc(bl1)));
    bl2 = fdec(__reduce_min_sync(0xffffffffu, fenc(bl2)));
    bh0 = fdec(__reduce_max_sync(0xffffffffu, fenc(bh0)));
    bh1 = fdec(__reduce_max_sync(0xffffffffu, fenc(bh1)));
    bh2 = fdec(__reduce_max_sync(0xffffffffu, fenc(bh2)));

    const float* p0 = P + (size_t)b*PNN*3;
    float px0=p0[0], py0=p0[1], pz0=p0[2];
    float cx = fmaf(g_L[0],px0, fmaf(g_L[1],py0, g_L[2]*pz0));
    float cy = fmaf(g_L[3],py0, g_L[4]*pz0);
    float cz = g_L[5]*pz0;
    if (t == 0) g_sel[b*NSS] = 0;
    __syncthreads();

    unsigned            wub  = 0xFFFFFFFFu;
    unsigned long long  wkey = 0ull;

    for (int j = 0; j < NSS-1; j++){
        float e0 = fmaxf(fmaxf(bl0-cx, cx-bh0), 0.f);
        float e1 = fmaxf(fmaxf(bl1-cy, cy-bh1), 0.f);
        float e2 = fmaxf(fmaxf(bl2-cz, cz-bh2), 0.f);
        float lb = fmaf(e0,e0, fmaf(e1,e1, e2*e2));

        if (__float_as_uint(lb) < wub){
            unsigned long long mcx2 = pk2(-cx,-cx);
            unsigned long long mcy2 = pk2(-cy,-cy);
            unsigned long long mcz2 = pk2(-cz,-cz);
            float gm[4]; float ub;
#pragma unroll
            for (int g = 0; g < 4; g++){
                int swo = (wid<<9) + (g<<7) + (lane<<2);
                ulonglong2 z2 = *(ulonglong2*)(smz + swo);
                float4 dd = *(float4*)(smd + swo);
                unsigned long long ax = add2(X2[2*g],   mcx2);
                unsigned long long ay = add2(Y2[2*g],   mcy2);
                unsigned long long az = add2(z2.x,      mcz2);
                unsigned long long d2 = fma2(ax,ax, fma2(ay,ay, mul2(az,az)));
                float d0, d1; upk2(d2, d0, d1);
                dd.x = fminf(dd.x, d0); dd.y = fminf(dd.y, d1);
                ax = add2(X2[2*g+1], mcx2);
                ay = add2(Y2[2*g+1], mcy2);
                az = add2(z2.y,      mcz2);
                d2 = fma2(ax,ax, fma2(ay,ay, mul2(az,az)));
                upk2(d2, d0, d1);
                dd.z = fminf(dd.z, d0); dd.w = fminf(dd.w, d1);
                *(float4*)(smd + swo) = dd;
                gm[g] = fmaxf(fmaxf(dd.x,dd.y), fmaxf(dd.z,dd.w));
            }
            ub = fmaxf(fmaxf(gm[0],gm[1]), fmaxf(gm[2],gm[3]));
            wub = __reduce_max_sync(0xffffffffu, __float_as_uint(ub));

            unsigned cand = 0u;
            if (__float_as_uint(ub) == wub){
#pragma unroll
                for (int g = 0; g < 4; g++){
                    if (__float_as_uint(gm[g]) == wub){
                        int swo = (wid<<9) + (g<<7) + (lane<<2);
                        float4 dd = *(float4*)(smd + swo);
                        int4   oo = *(int4*)  (smo + swo);
                        unsigned rb = (unsigned)(t*FPS_K + g*4);
                        if (__float_as_uint(dd.x)==wub)
                            cand = max(cand, ((0x3FFFu-(unsigned)oo.x)<<14)|(rb+0));
                        if (__float_as_uint(dd.y)==wub)
                            cand = max(cand, ((0x3FFFu-(unsigned)oo.y)<<14)|(rb+1));
                        if (__float_as_uint(dd.z)==wub)
                            cand = max(cand, ((0x3FFFu-(unsigned)oo.z)<<14)|(rb+2));
                        if (__float_as_uint(dd.w)==wub)
                            cand = max(cand, ((0x3FFFu-(unsigned)oo.w)<<14)|(rb+3));
                    }
                }
            }
            unsigned wlo = __reduce_max_sync(0xffffffffu, cand);
            wkey = ((unsigned long long)wub << 32) | wlo;
        }
        if (lane == 0) slot[((j&1)<<5) + wid] = wkey;
        __syncthreads();

        unsigned long long kk = slot[((j&1)<<5) + lane];
        unsigned hi = (unsigned)(kk >> 32), lo = (unsigned)kk;
        unsigned gh = __reduce_max_sync(0xffffffffu, hi);
        unsigned gl = __reduce_max_sync(0xffffffffu, (hi==gh) ? lo : 0u);

        int r = (int)(gl & 0x3FFFu);
        float4 cp = gp[r];
        cx = cp.x; cy = cp.y; cz = cp.z;
        if (t == 0) g_sel[b*NSS + j + 1] = (int)(0x3FFFu - (gl >> 14));
    }
}

// ---------------- h1 build: rank-4 update per selected point ---------------
__global__ __launch_bounds__(256) void k_h1(const float* __restrict__ P){
    int f = blockIdx.x * 256 + threadIdx.x;       // float4 idx, 2048*96 total
    int n = f / 96, c4 = (f % 96) * 4;
    int b = n >> 8;
    int sidx = g_sel[n];
    const float* pp = P + ((size_t)b*PNN + sidx)*3;
    float x = pp[0], y = pp[1], z = pp[2];
    float4 a0 = *(const float4*)&g_A0[c4];
    float4 a1 = *(const float4*)&g_A1[c4];
    float4 a2 = *(const float4*)&g_A2[c4];
    float4 a3 = *(const float4*)&g_A3[c4];
    float4 gc = *(const float4*)&g_gfc[b*HIDC + c4];
    float4 v;
    v.x = gc.x + fmaf(x,a0.x, fmaf(y,a1.x, fmaf(z,a2.x, a3.x)));
    v.y = gc.y + fmaf(x,a0.y, fmaf(y,a1.y, fmaf(z,a2.y, a3.y)));
    v.z = gc.z + fmaf(x,a0.z, fmaf(y,a1.z, fmaf(z,a2.z, a3.z)));
    v.w = gc.w + fmaf(x,a0.w, fmaf(y,a1.w, fmaf(z,a2.w, a3.w)));
    *(float4*)&g_h1[(size_t)n*HIDC + c4] = v;
}

// ---------------- BN stats partial pass ------------------------------------
__global__ __launch_bounds__(256) void k_statsp(int mode){
    const float* X = (mode == 0) ? g_h1 : g_h2;
    __shared__ float ssum[256], ssq[256];
    int cl = threadIdx.x & 31;
    int rg = threadIdx.x >> 5;
    int c  = blockIdx.x * 32 + cl;
    int r0 = blockIdx.y * 256;
    float s = 0.f, q = 0.f;
    for (int r = r0 + rg; r < r0 + 256; r += 8){
        float v = X[(size_t)r*HIDC + c];
        s += v; q = fmaf(v, v, q);
    }
    ssum[threadIdx.x] = s; ssq[threadIdx.x] = q;
    __syncthreads();
    if (rg == 0){
#pragma unroll
        for (int i = 1; i < 8; i++){ s += ssum[i*32 + cl]; q += ssq[i*32 + cl]; }
        g_psum[blockIdx.y*HIDC + c] = s;
        g_psq [blockIdx.y*HIDC + c] = q;
    }
}

// ---------------- GEMM2 (BN1 stats fused in prologue) ----------------------
__global__ __launch_bounds__(256) void k_gemm(const float* __restrict__ Wt,
                                              const float* __restrict__ bias,
                                              const float* __restrict__ g1,
                                              const float* __restrict__ be1)
{
    const int BM=64, BN=64, BK=16, K=HIDC;
    __shared__ float As[BK][BM];
    __shared__ float Bs[BK][BN];
    __shared__ float ssc[HIDC], ssh[HIDC];

    for (int c = threadIdx.x; c < HIDC; c += 256){
        float s = 0.f, q = 0.f;
#pragma unroll
        for (int i = 0; i < 8; i++){
            s += g_psum[i*HIDC + c];
            q += g_psq [i*HIDC + c];
        }
        float mean = s * (1.f/MROWS);
        float var  = q * (1.f/MROWS) - mean*mean;
        float sv   = g1[c] * rsqrtf(var + EPSC);
        ssc[c] = sv;
        ssh[c] = fmaf(-mean, sv, be1[c]);
    }
    __syncthreads();

    int tx = threadIdx.x & 15;
    int ty = threadIdx.x >> 4;
    int m0 = blockIdx.y * BM;
    int n0 = blockIdx.x * BN;
    int lr = threadIdx.x >> 2;
    int lk = (threadIdx.x & 3) * 4;

    float acc[4][4];
#pragma unroll
    for (int i=0;i<4;i++)
#pragma unroll
        for (int j=0;j<4;j++) acc[i][j]=0.f;

    for (int k0 = 0; k0 < K; k0 += BK){
        float4 av = *(const float4*)&g_h1[(size_t)(m0+lr)*K + k0 + lk];
        float4 sv = *(const float4*)&ssc[k0+lk];
        float4 hv = *(const float4*)&ssh[k0+lk];
        av.x = fmaxf(fmaf(av.x, sv.x, hv.x), 0.f);
        av.y = fmaxf(fmaf(av.y, sv.y, hv.y), 0.f);
        av.z = fmaxf(fmaf(av.z, sv.z, hv.z), 0.f);
        av.w = fmaxf(fmaf(av.w, sv.w, hv.w), 0.f);
        float4 bv = *(const float4*)&Wt[(size_t)(n0+lr)*K + k0 + lk];
        As[lk+0][lr]=av.x; As[lk+1][lr]=av.y; As[lk+2][lr]=av.z; As[lk+3][lr]=av.w;
        Bs[lk+0][lr]=bv.x; Bs[lk+1][lr]=bv.y; Bs[lk+2][lr]=bv.z; Bs[lk+3][lr]=bv.w;
        __syncthreads();
#pragma unroll
        for (int kk = 0; kk < BK; kk++){
            float4 a = *(const float4*)&As[kk][ty*4];
            float4 b = *(const float4*)&Bs[kk][tx*4];
            acc[0][0]=fmaf(a.x,b.x,acc[0][0]); acc[0][1]=fmaf(a.x,b.y,acc[0][1]);
            acc[0][2]=fmaf(a.x,b.z,acc[0][2]); acc[0][3]=fmaf(a.x,b.w,acc[0][3]);
            acc[1][0]=fmaf(a.y,b.x,acc[1][0]); acc[1][1]=fmaf(a.y,b.y,acc[1][1]);
            acc[1][2]=fmaf(a.y,b.z,acc[1][2]); acc[1][3]=fmaf(a.y,b.w,acc[1][3]);
            acc[2][0]=fmaf(a.z,b.x,acc[2][0]); acc[2][1]=fmaf(a.z,b.y,acc[2][1]);
            acc[2][2]=fmaf(a.z,b.z,acc[2][2]); acc[2][3]=fmaf(a.z,b.w,acc[2][3]);
            acc[3][0]=fmaf(a.w,b.x,acc[3][0]); acc[3][1]=fmaf(a.w,b.y,acc[3][1]);
            acc[3][2]=fmaf(a.w,b.z,acc[3][2]); acc[3][3]=fmaf(a.w,b.w,acc[3][3]);
        }
        __syncthreads();
    }
    float4 bb = *(const float4*)&bias[n0 + tx*4];
#pragma unroll
    for (int i = 0; i < 4; i++){
        float4 o;
        o.x = acc[i][0] + bb.x; o.y = acc[i][1] + bb.y;
        o.z = acc[i][2] + bb.z; o.w = acc[i][3] + bb.w;
        *(float4*)&g_h2[(size_t)(m0 + ty*4 + i)*HIDC + n0 + tx*4] = o;
    }
}

// ---------------- final: BN2 stats folded per-block + relu(bn2(h2)) --------
__global__ __launch_bounds__(256) void k_final(const float* __restrict__ g2,
                                               const float* __restrict__ be2,
                                               float* __restrict__ out){
    __shared__ float ssc[HIDC], ssh[HIDC];
    for (int c = threadIdx.x; c < HIDC; c += 256){
        float s = 0.f, q = 0.f;
#pragma unroll
        for (int i = 0; i < 8; i++){
            s += g_psum[i*HIDC + c];
            q += g_psq [i*HIDC + c];
        }
        float mean = s * (1.f/MROWS);
        float var  = q * (1.f/MROWS) - mean*mean;
        float sv   = g2[c] * rsqrtf(var + EPSC);
        ssc[c] = sv;
        ssh[c] = fmaf(-mean, sv, be2[c]);
    }
    __syncthreads();

    int i = blockIdx.x * 256 + threadIdx.x;
    float4 v = ((const float4*)g_h2)[i];
    int c = (i*4) % HIDC;
    v.x = fmaxf(fmaf(v.x, ssc[c+0], ssh[c+0]), 0.f);
    v.y = fmaxf(fmaf(v.y, ssc[c+1], ssh[c+1]), 0.f);
    v.z = fmaxf(fmaf(v.z, ssc[c+2], ssh[c+2]), 0.f);
    v.w = fmaxf(fmaf(v.w, ssc[c+3], ssh[c+3]), 0.f);
    ((float4*)out)[i] = v;
}

// ---------------- launch ---------------------------------------------------
extern "C" void kernel_launch(void* const* d_in, const int* in_sizes, int n_in,
                              void* d_out, int out_size){
    (void)in_sizes; (void)n_in; (void)out_size;
    const float* p   = (const float*)d_in[0];
    const float* pf  = (const float*)d_in[2];
    const float* Wf  = (const float*)d_in[3];
    const float* bf  = (const float*)d_in[4];
    const float* Wc  = (const float*)d_in[5];
    const float* bc  = (const float*)d_in[6];
    const float* W1  = (const float*)d_in[7];
    const float* b1  = (const float*)d_in[8];
    const float* g1  = (const float*)d_in[9];
    const float* be1 = (const float*)d_in[10];
    const float* W2  = (const float*)d_in[11];
    const float* b2  = (const float*)d_in[12];
    const float* g2  = (const float*)d_in[13];
    const float* be2 = (const float*)d_in[14];
    float* out = (float*)d_out;

    cudaFuncSetAttribute(k_fps5, cudaFuncAttributeMaxDynamicSharedMemorySize,
                         FPS_SMEM_FLOATS * (int)sizeof(float));

    k_setup1<<<1 + BB, 384>>>(Wc, pf, Wf, bf);
    k_setup2<<<dim3(HIDC, 2), 256>>>(Wc, bc, W1, b1);
    k_prep<<<BB, 1024>>>(p);
    k_fps5<<<BB, FPS_T, FPS_SMEM_FLOATS * sizeof(float)>>>(p);
    k_h1<<<(MROWS*96)/256, 256>>>(p);
    k_statsp<<<dim3(HIDC/32, 8), 256>>>(0);
    k_gemm<<<dim3(HIDC/64, MROWS/64), 256>>>(W2, b2, g1, be1);   // BN1 fused
    k_statsp<<<dim3(HIDC/32, 8), 256>>>(1);
    k_final<<<(MROWS*HIDC/4)/256, 256>>>(g2, be2, out);
}